// round 11
// baseline (speedup 1.0000x reference)
#include <cuda_runtime.h>
#include <cuda_fp16.h>
#include <cstdint>
#include <math.h>

// ===========================================================================
// B=8, S=2048, D=1024 fp32.
//   scores = causal(x x^T / 32); P = softmax(scores); attn = P x; y = attn W^T
// GEMM engine: mma.sync.m16n8k16 FP16, CTA tile 128x128 (4 warps x 64x64),
// CKH=32, 5-stage cp.async pipeline, both-kstep fragment prefetch,
// ldmatrix b16 fragments, 2 CTAs/SM. fp16 scores, in-place no-max softmax.
// ===========================================================================

#define BATCH 8
#define SEQ   2048
#define DIM   1024

#define TM 128
#define TN 128
#define CKH 32                 // halves per chunk (64 B rows)
#define LDH 40                 // smem row stride in halves (80 B, conflict-free)
#define NSTAGE 5
#define A_BYTES (TM * LDH * 2)            // 10240
#define B_BYTES (TN * LDH * 2)            // 10240
#define STAGE_BYTES (A_BYTES + B_BYTES)   // 20480
#define DSMEM_SZ (NSTAGE * STAGE_BYTES)   // 102400 B (x2 CTAs = 200 KB)

static __device__ __half g_scoresh[(long)BATCH * SEQ * SEQ]; // fp16 scores -> P (in place)
static __device__ __half g_xh[(long)BATCH * SEQ * DIM];      // fp16 x
static __device__ __half g_xTh[(long)BATCH * DIM * SEQ];     // fp16 x^T
static __device__ __half g_attnh[(long)BATCH * SEQ * DIM];   // fp16 attn
static __device__ __half g_Wh[DIM * DIM];                    // fp16 W

// ---------------------------------------------------------------- helpers --
__device__ __forceinline__ uint32_t smem_u32(const void* p) {
    uint32_t a;
    asm("{ .reg .u64 t; cvta.to.shared.u64 t, %1; cvt.u32.u64 %0, t; }"
        : "=r"(a) : "l"(p));
    return a;
}
__device__ __forceinline__ void cp_async16(uint32_t s, const void* g) {
    asm volatile("cp.async.cg.shared.global [%0], [%1], 16;" :: "r"(s), "l"(g));
}
#define CP_COMMIT() asm volatile("cp.async.commit_group;" ::: "memory")
#define CP_WAIT(n)  asm volatile("cp.async.wait_group %0;" :: "n"(n) : "memory")

__device__ __forceinline__ void mma_f16(float c[4], const uint32_t a[4], const uint32_t b[2]) {
    asm volatile(
        "mma.sync.aligned.m16n8k16.row.col.f32.f16.f16.f32 "
        "{%0,%1,%2,%3}, {%4,%5,%6,%7}, {%8,%9}, {%0,%1,%2,%3};"
        : "+f"(c[0]), "+f"(c[1]), "+f"(c[2]), "+f"(c[3])
        : "r"(a[0]), "r"(a[1]), "r"(a[2]), "r"(a[3]), "r"(b[0]), "r"(b[1]));
}
__device__ __forceinline__ void ldsm4(uint32_t r[4], uint32_t addr) {
    asm volatile("ldmatrix.sync.aligned.m8n8.x4.shared.b16 {%0,%1,%2,%3}, [%4];"
                 : "=r"(r[0]), "=r"(r[1]), "=r"(r[2]), "=r"(r[3]) : "r"(addr));
}

// ---------------------------------------------------------------- GEMM NT --
// C[m,n] = scale * sum_k A[m,k] * B[n,k]   (A,B fp16 K-contiguous)
__global__ __launch_bounds__(128, 2) void gemm_h(
    const __half* __restrict__ A, const __half* __restrict__ B, void* __restrict__ Cv,
    int K, int lda, int ldb, int ldc,
    long sA, long sB, long sC,
    float scale, int causal, int klimit, int outHalf)
{
    extern __shared__ char smem[];

    A += (long)blockIdx.z * sA;
    B += (long)blockIdx.z * sB;

    const int m0 = blockIdx.y * TM;
    const int n0 = blockIdx.x * TN;
    if (causal && n0 > m0 + TM - 1) return;
    const int kmax = klimit ? min(K, m0 + TM) : K;
    const int nch  = kmax / CKH;

    const int tid   = threadIdx.x;
    const int lane  = tid & 31;
    const int wid   = tid >> 5;            // 0..3
    const int warpM = wid & 1;
    const int warpN = wid >> 1;
    const int qr    = lane >> 2;
    const int qk    = lane & 3;

    const uint32_t sbase = smem_u32(smem);

    // ldmatrix lane addressing (validated Round 9/10)
    const int a_row_l = (((lane >> 3) & 1) << 3) + (lane & 7);
    const int a_kh    = ((lane >> 4) & 1) << 3;
    const int b_row_l = (((lane >> 4) & 1) << 3) + (lane & 7);
    const int b_kh    = ((lane >> 3) & 1) << 3;
    uint32_t a_off[4], b_off[4];
#pragma unroll
    for (int mf = 0; mf < 4; mf++)
        a_off[mf] = (uint32_t)((warpM * 64 + mf * 16 + a_row_l) * (LDH * 2) + a_kh * 2);
#pragma unroll
    for (int p = 0; p < 4; p++)
        b_off[p] = (uint32_t)(A_BYTES + (warpN * 64 + p * 16 + b_row_l) * (LDH * 2) + b_kh * 2);

    float acc[32][4];
#pragma unroll
    for (int i = 0; i < 32; i++)
#pragma unroll
        for (int j = 0; j < 4; j++) acc[i][j] = 0.f;

    auto load_stage = [&](int s, int c) {
        const uint32_t st = sbase + (uint32_t)(s * STAGE_BYTES);
        const char* gA = (const char*)(A + (long)m0 * lda + c * CKH);
        const char* gB = (const char*)(B + (long)n0 * ldb + c * CKH);
#pragma unroll
        for (int i = 0; i < 4; i++) {
            int idx = tid + i * 128;         // 0..511
            int row = idx >> 2;
            int ch  = (idx & 3) << 4;
            cp_async16(st + (uint32_t)(row * (LDH * 2)) + ch,
                       gA + (long)row * lda * 2 + ch);
        }
#pragma unroll
        for (int i = 0; i < 4; i++) {
            int idx = tid + i * 128;
            int row = idx >> 2;
            int ch  = (idx & 3) << 4;
            cp_async16(st + (uint32_t)(A_BYTES + row * (LDH * 2)) + ch,
                       gB + (long)row * ldb * 2 + ch);
        }
    };

#pragma unroll
    for (int s = 0; s < NSTAGE - 1; s++) {
        if (s < nch) load_stage(s, s);
        CP_COMMIT();
    }

    for (int c = 0; c < nch; c++) {
        CP_WAIT(NSTAGE - 2);
        __syncthreads();

        const int pf = c + NSTAGE - 1;
        if (pf < nch) load_stage(pf % NSTAGE, pf);
        CP_COMMIT();

        const uint32_t st = sbase + (uint32_t)((c % NSTAGE) * STAGE_BYTES);

        // load ALL fragments for both ksteps, then burst 64 MMAs
        uint32_t a[2][4][4], b[2][4][4];
#pragma unroll
        for (int ks = 0; ks < 2; ks++) {
            const uint32_t ko = ks * 32;     // 16 halves * 2 bytes
#pragma unroll
            for (int mf = 0; mf < 4; mf++)
                ldsm4(a[ks][mf], st + a_off[mf] + ko);
#pragma unroll
            for (int p = 0; p < 4; p++)
                ldsm4(b[ks][p], st + b_off[p] + ko);
        }
#pragma unroll
        for (int ks = 0; ks < 2; ks++)
#pragma unroll
            for (int mf = 0; mf < 4; mf++)
#pragma unroll
                for (int nf = 0; nf < 8; nf++)
                    mma_f16(acc[mf * 8 + nf], a[ks][mf], &b[ks][nf >> 1][(nf & 1) << 1]);
    }

    // epilogue
    if (outHalf) {
        __half* C = (__half*)Cv + (long)blockIdx.z * sC;
#pragma unroll
        for (int mf = 0; mf < 4; mf++) {
            const int m = m0 + warpM * 64 + mf * 16 + qr;
#pragma unroll
            for (int nf = 0; nf < 8; nf++) {
                const int n = n0 + warpN * 64 + nf * 8 + 2 * qk;
                float* c0 = acc[mf * 8 + nf];
                *(__half2*)&C[(long)m * ldc + n] =
                    __floats2half2_rn(c0[0] * scale, c0[1] * scale);
                *(__half2*)&C[(long)(m + 8) * ldc + n] =
                    __floats2half2_rn(c0[2] * scale, c0[3] * scale);
            }
        }
    } else {
        float* C = (float*)Cv + (long)blockIdx.z * sC;
#pragma unroll
        for (int mf = 0; mf < 4; mf++) {
            const int m = m0 + warpM * 64 + mf * 16 + qr;
#pragma unroll
            for (int nf = 0; nf < 8; nf++) {
                const int n = n0 + warpN * 64 + nf * 8 + 2 * qk;
                float* c0 = acc[mf * 8 + nf];
                *(float2*)&C[(long)m * ldc + n] =
                    make_float2(c0[0] * scale, c0[1] * scale);
                *(float2*)&C[(long)(m + 8) * ldc + n] =
                    make_float2(c0[2] * scale, c0[3] * scale);
            }
        }
    }
}

// ---------------------------------------------------------------- prep -----
__global__ __launch_bounds__(256) void conv_x(
    const float* __restrict__ x, __half* __restrict__ xh, __half* __restrict__ xT)
{
    __shared__ float t[32][33];
    const int b  = blockIdx.z;
    const int s0 = blockIdx.x * 32;
    const int d0 = blockIdx.y * 32;
    const float* xb = x + (long)b * SEQ * DIM;
    __half* xhb = xh + (long)b * SEQ * DIM;
    __half* xTb = xT + (long)b * DIM * SEQ;
    const int tx = threadIdx.x & 31;
    const int tg = threadIdx.x >> 5;
#pragma unroll
    for (int r = 0; r < 4; r++) {
        int row = tg * 4 + r;
        float v = xb[(long)(s0 + row) * DIM + d0 + tx];
        t[row][tx] = v;
        xhb[(long)(s0 + row) * DIM + d0 + tx] = __float2half_rn(v);
    }
    __syncthreads();
#pragma unroll
    for (int r = 0; r < 4; r++) {
        int row = tg * 4 + r;
        xTb[(long)(d0 + row) * SEQ + s0 + tx] = __float2half_rn(t[tx][row]);
    }
}

__global__ __launch_bounds__(256) void conv_W(const float* __restrict__ W,
                                              __half* __restrict__ Wh, long n4)
{
    long i = (long)blockIdx.x * blockDim.x + threadIdx.x;
    if (i >= n4) return;
    float4 v = ((const float4*)W)[i];
    __half2* o = (__half2*)Wh + i * 2;
    o[0] = __floats2half2_rn(v.x, v.y);
    o[1] = __floats2half2_rn(v.z, v.w);
}

// ---------------------------------------------------------------- softmax --
// causal softmax in place (fp16), no max-subtraction (scores are O(±10),
// exp in fp32 is safe; softmax is shift-invariant so result is identical).
__global__ __launch_bounds__(256) void softmax_kernel(__half* __restrict__ scores)
{
    const long row = blockIdx.x;
    const int  q   = (int)(row % SEQ);
    __half* p = scores + row * (long)SEQ;
    const int tid  = threadIdx.x;
    const int len  = q + 1;
    const int lenR = ((q >> 7) + 1) << 7;

    __shared__ float red[8];

    float v[8];
    float s = 0.f;
#pragma unroll
    for (int j = 0; j < 8; j++) {
        int i = tid + j * 256;
        v[j] = (i < len) ? __expf(__half2float(p[i])) : 0.f;
        s += v[j];
    }
#pragma unroll
    for (int o = 16; o > 0; o >>= 1) s += __shfl_xor_sync(0xffffffffu, s, o);
    if ((tid & 31) == 0) red[tid >> 5] = s;
    __syncthreads();
    float s_all = 0.f;
#pragma unroll
    for (int w = 0; w < 8; w++) s_all += red[w];
    const float inv = 1.f / s_all;

#pragma unroll
    for (int j = 0; j < 8; j++) {
        int i = tid + j * 256;
        if (i < lenR)
            p[i] = __float2half_rn((i < len) ? v[j] * inv : 0.f);
    }
}

// ---------------------------------------------------------------------------
extern "C" void kernel_launch(void* const* d_in, const int* in_sizes, int n_in,
                              void* d_out, int out_size)
{
    const float* x = (const float*)d_in[0];
    const float* W = (const float*)d_in[1];
    float* out = (float*)d_out;

    __half *scoresh, *xh, *xTh, *attnh, *Wh;
    cudaGetSymbolAddress((void**)&scoresh, g_scoresh);
    cudaGetSymbolAddress((void**)&xh, g_xh);
    cudaGetSymbolAddress((void**)&xTh, g_xTh);
    cudaGetSymbolAddress((void**)&attnh, g_attnh);
    cudaGetSymbolAddress((void**)&Wh, g_Wh);

    cudaFuncSetAttribute(gemm_h,
                         cudaFuncAttributeMaxDynamicSharedMemorySize, DSMEM_SZ);

    const float scale = 1.0f / 32.0f;

    conv_x<<<dim3(SEQ / 32, DIM / 32, BATCH), 256>>>(x, xh, xTh);
    conv_W<<<(DIM * DIM / 4 + 255) / 256, 256>>>(W, Wh, (long)DIM * DIM / 4);

    // 1) scores = scale * x x^T  (fp16 out, causal tiles only)
    gemm_h<<<dim3(SEQ / TN, SEQ / TM, BATCH), 128, DSMEM_SZ>>>(
        xh, xh, scoresh, DIM, DIM, DIM, SEQ,
        (long)SEQ * DIM, (long)SEQ * DIM, (long)SEQ * SEQ,
        scale, 1, 0, 1);

    // 2) causal softmax in place -> P
    softmax_kernel<<<BATCH * SEQ, 256>>>(scoresh);

    // 3) attn = P x  (fp16 out, k-limited)
    gemm_h<<<dim3(DIM / TN, SEQ / TM, BATCH), 128, DSMEM_SZ>>>(
        scoresh, xTh, attnh, SEQ, SEQ, SEQ, DIM,
        (long)SEQ * SEQ, (long)DIM * SEQ, (long)SEQ * DIM,
        1.0f, 0, 1, 1);

    // 4) y = attn W^T  (fp32 out)
    gemm_h<<<dim3(DIM / TN, (BATCH * SEQ) / TM, 1), 128, DSMEM_SZ>>>(
        attnh, Wh, out, DIM, DIM, DIM, DIM,
        0, 0, 0,
        1.0f, 0, 0, 0);
}

// round 14
// speedup vs baseline: 1.0574x; 1.0574x over previous
#include <cuda_runtime.h>
#include <cuda_fp16.h>
#include <cstdint>
#include <math.h>

// ===========================================================================
// B=8, S=2048, D=1024 fp32.
//   scores = causal(x x^T / 32); P = softmax(scores); attn = P x; y = attn W^T
// GEMM engine: mma.sync.m16n8k16 FP16, CTA tile 128x128 (4 warps x 64x64),
// CKH=32, 4-stage cp.async pipeline (Round-10 proven schedule), ldmatrix b16,
// 2 CTAs/SM, PERSISTENT grid with in-kernel tile decode:
//   mode 1 (scores): triangular causal tile list (no dead CTAs)
//   mode 2 (PV):     longest-k-first (LPT) ordering for the k-limited tiles
//   mode 0 (proj):   linear
// ===========================================================================

#define BATCH 8
#define SEQ   2048
#define DIM   1024

#define TM 128
#define TN 128
#define CKH 32                 // halves per chunk (64 B rows)
#define LDH 40                 // smem row stride in halves (80 B, conflict-free)
#define NSTAGE 4
#define A_BYTES (TM * LDH * 2)            // 10240
#define B_BYTES (TN * LDH * 2)            // 10240
#define STAGE_BYTES (A_BYTES + B_BYTES)   // 20480
#define DSMEM_SZ (NSTAGE * STAGE_BYTES)   // 81920 B (x2 CTAs = 160 KB)

static __device__ __half g_scoresh[(long)BATCH * SEQ * SEQ]; // fp16 scores -> P in place
static __device__ __half g_xh[(long)BATCH * SEQ * DIM];
static __device__ __half g_xTh[(long)BATCH * DIM * SEQ];
static __device__ __half g_attnh[(long)BATCH * SEQ * DIM];
static __device__ __half g_Wh[DIM * DIM];

// ---------------------------------------------------------------- helpers --
__device__ __forceinline__ uint32_t smem_u32(const void* p) {
    uint32_t a;
    asm("{ .reg .u64 t; cvta.to.shared.u64 t, %1; cvt.u32.u64 %0, t; }"
        : "=r"(a) : "l"(p));
    return a;
}
__device__ __forceinline__ void cp_async16(uint32_t s, const void* g) {
    asm volatile("cp.async.cg.shared.global [%0], [%1], 16;" :: "r"(s), "l"(g));
}
#define CP_COMMIT() asm volatile("cp.async.commit_group;" ::: "memory")
#define CP_WAIT(n)  asm volatile("cp.async.wait_group %0;" :: "n"(n) : "memory")

__device__ __forceinline__ void mma_f16(float c[4], const uint32_t a[4], const uint32_t b[2]) {
    asm volatile(
        "mma.sync.aligned.m16n8k16.row.col.f32.f16.f16.f32 "
        "{%0,%1,%2,%3}, {%4,%5,%6,%7}, {%8,%9}, {%0,%1,%2,%3};"
        : "+f"(c[0]), "+f"(c[1]), "+f"(c[2]), "+f"(c[3])
        : "r"(a[0]), "r"(a[1]), "r"(a[2]), "r"(a[3]), "r"(b[0]), "r"(b[1]));
}
__device__ __forceinline__ void ldsm4(uint32_t r[4], uint32_t addr) {
    asm volatile("ldmatrix.sync.aligned.m8n8.x4.shared.b16 {%0,%1,%2,%3}, [%4];"
                 : "=r"(r[0]), "=r"(r[1]), "=r"(r[2]), "=r"(r[3]) : "r"(addr));
}

// ---------------------------------------------------------------- GEMM NT --
// C[m,n] = scale * sum_k A[m,k] * B[n,k]   (A,B fp16 K-contiguous), persistent.
__global__ __launch_bounds__(128, 2) void gemm_h(
    const __half* __restrict__ A, const __half* __restrict__ B, void* __restrict__ Cv,
    int K, int lda, int ldb, int ldc,
    long sA, long sB, long sC,
    float scale, int mode, int ntm, int ntn, int nb, int tpb, int ntiles,
    int outHalf)
{
    extern __shared__ char smem[];

    const int tid   = threadIdx.x;
    const int lane  = tid & 31;
    const int wid   = tid >> 5;            // 0..3
    const int warpM = wid & 1;
    const int warpN = wid >> 1;
    const int qr    = lane >> 2;
    const int qk    = lane & 3;

    const uint32_t sbase = smem_u32(smem);

    // ldmatrix lane addressing (validated Rounds 9-11)
    const int a_row_l = (((lane >> 3) & 1) << 3) + (lane & 7);
    const int a_kh    = ((lane >> 4) & 1) << 3;
    const int b_row_l = (((lane >> 4) & 1) << 3) + (lane & 7);
    const int b_kh    = ((lane >> 3) & 1) << 3;
    uint32_t a_off[4], b_off[4];
#pragma unroll
    for (int mf = 0; mf < 4; mf++)
        a_off[mf] = (uint32_t)((warpM * 64 + mf * 16 + a_row_l) * (LDH * 2) + a_kh * 2);
#pragma unroll
    for (int p = 0; p < 4; p++)
        b_off[p] = (uint32_t)(A_BYTES + (warpN * 64 + p * 16 + b_row_l) * (LDH * 2) + b_kh * 2);

    for (int t = blockIdx.x; t < ntiles; t += gridDim.x) {
        // ---- tile decode ----
        int b, my, nx;
        if (mode == 1) {                       // causal triangular list
            b = t / tpb;
            int r = t - b * tpb;
            int lo = (int)((sqrtf(8.f * (float)r + 1.f) - 1.f) * 0.5f);
            while ((lo + 1) * (lo + 2) / 2 <= r) lo++;
            while (lo * (lo + 1) / 2 > r) lo--;
            my = lo;
            nx = r - lo * (lo + 1) / 2;
        } else if (mode == 2) {                // k-limited, longest rows first
            int pg = ntn * nb;
            my = ntm - 1 - t / pg;
            int rem = t - (t / pg) * pg;
            nx = rem / nb;
            b  = rem - nx * nb;
        } else {                               // dense linear
            b = 0;
            my = t / ntn;
            nx = t - my * ntn;
        }

        const __half* Ab = A + (long)b * sA;
        const __half* Bb = B + (long)b * sB;
        const int m0 = my * TM;
        const int n0 = nx * TN;
        const int kmax = (mode == 2) ? min(K, m0 + TM) : K;
        const int nch  = kmax / CKH;

        float acc[32][4];
#pragma unroll
        for (int i = 0; i < 32; i++)
#pragma unroll
            for (int j = 0; j < 4; j++) acc[i][j] = 0.f;

        auto load_stage = [&](int s, int c) {
            const uint32_t st = sbase + (uint32_t)(s * STAGE_BYTES);
            const char* gA = (const char*)(Ab + (long)m0 * lda + c * CKH);
            const char* gB = (const char*)(Bb + (long)n0 * ldb + c * CKH);
#pragma unroll
            for (int i = 0; i < 4; i++) {
                int idx = tid + i * 128;       // 0..511
                int row = idx >> 2;
                int ch  = (idx & 3) << 4;
                cp_async16(st + (uint32_t)(row * (LDH * 2)) + ch,
                           gA + (long)row * lda * 2 + ch);
            }
#pragma unroll
            for (int i = 0; i < 4; i++) {
                int idx = tid + i * 128;
                int row = idx >> 2;
                int ch  = (idx & 3) << 4;
                cp_async16(st + (uint32_t)(A_BYTES + row * (LDH * 2)) + ch,
                           gB + (long)row * ldb * 2 + ch);
            }
        };

#pragma unroll
        for (int s = 0; s < NSTAGE - 1; s++) {
            if (s < nch) load_stage(s, s);
            CP_COMMIT();
        }

        for (int c = 0; c < nch; c++) {
            CP_WAIT(NSTAGE - 2);
            __syncthreads();

            const int pf = c + NSTAGE - 1;
            if (pf < nch) load_stage(pf % NSTAGE, pf);
            CP_COMMIT();

            const uint32_t st = sbase + (uint32_t)((c % NSTAGE) * STAGE_BYTES);

#pragma unroll
            for (int kk = 0; kk < CKH; kk += 16) {
                uint32_t a[4][4], bb[4][4];
#pragma unroll
                for (int mf = 0; mf < 4; mf++)
                    ldsm4(a[mf], st + a_off[mf] + kk * 2);
#pragma unroll
                for (int p = 0; p < 4; p++)
                    ldsm4(bb[p], st + b_off[p] + kk * 2);
#pragma unroll
                for (int mf = 0; mf < 4; mf++)
#pragma unroll
                    for (int nf = 0; nf < 8; nf++)
                        mma_f16(acc[mf * 8 + nf], a[mf], &bb[nf >> 1][(nf & 1) << 1]);
            }
        }

        // epilogue
        if (outHalf) {
            __half* C = (__half*)Cv + (long)b * sC;
#pragma unroll
            for (int mf = 0; mf < 4; mf++) {
                const int m = m0 + warpM * 64 + mf * 16 + qr;
#pragma unroll
                for (int nf = 0; nf < 8; nf++) {
                    const int n = n0 + warpN * 64 + nf * 8 + 2 * qk;
                    float* c0 = acc[mf * 8 + nf];
                    *(__half2*)&C[(long)m * ldc + n] =
                        __floats2half2_rn(c0[0] * scale, c0[1] * scale);
                    *(__half2*)&C[(long)(m + 8) * ldc + n] =
                        __floats2half2_rn(c0[2] * scale, c0[3] * scale);
                }
            }
        } else {
            float* C = (float*)Cv + (long)b * sC;
#pragma unroll
            for (int mf = 0; mf < 4; mf++) {
                const int m = m0 + warpM * 64 + mf * 16 + qr;
#pragma unroll
                for (int nf = 0; nf < 8; nf++) {
                    const int n = n0 + warpN * 64 + nf * 8 + 2 * qk;
                    float* c0 = acc[mf * 8 + nf];
                    *(float2*)&C[(long)m * ldc + n] =
                        make_float2(c0[0] * scale, c0[1] * scale);
                    *(float2*)&C[(long)(m + 8) * ldc + n] =
                        make_float2(c0[2] * scale, c0[3] * scale);
                }
            }
        }

        // drain async pipe + protect smem slots before next tile's prologue
        CP_WAIT(0);
        __syncthreads();
    }
}

// ---------------------------------------------------------------- prep -----
__global__ __launch_bounds__(256) void conv_x(
    const float* __restrict__ x, __half* __restrict__ xh, __half* __restrict__ xT)
{
    __shared__ float t[32][33];
    const int b  = blockIdx.z;
    const int s0 = blockIdx.x * 32;
    const int d0 = blockIdx.y * 32;
    const float* xb = x + (long)b * SEQ * DIM;
    __half* xhb = xh + (long)b * SEQ * DIM;
    __half* xTb = xT + (long)b * DIM * SEQ;
    const int tx = threadIdx.x & 31;
    const int tg = threadIdx.x >> 5;
#pragma unroll
    for (int r = 0; r < 4; r++) {
        int row = tg * 4 + r;
        float v = xb[(long)(s0 + row) * DIM + d0 + tx];
        t[row][tx] = v;
        xhb[(long)(s0 + row) * DIM + d0 + tx] = __float2half_rn(v);
    }
    __syncthreads();
#pragma unroll
    for (int r = 0; r < 4; r++) {
        int row = tg * 4 + r;
        xTb[(long)(d0 + row) * SEQ + s0 + tx] = __float2half_rn(t[tx][row]);
    }
}

__global__ __launch_bounds__(256) void conv_W(const float* __restrict__ W,
                                              __half* __restrict__ Wh, long n4)
{
    long i = (long)blockIdx.x * blockDim.x + threadIdx.x;
    if (i >= n4) return;
    float4 v = ((const float4*)W)[i];
    __half2* o = (__half2*)Wh + i * 2;
    o[0] = __floats2half2_rn(v.x, v.y);
    o[1] = __floats2half2_rn(v.z, v.w);
}

// ---------------------------------------------------------------- softmax --
// in-place causal softmax (fp16), no max subtraction (scores O(±32), safe in
// fp32 exp; softmax is shift-invariant). Writes only cols < roundUp(q+1,128).
__global__ __launch_bounds__(256) void softmax_kernel(__half* __restrict__ scores)
{
    const long row = blockIdx.x;
    const int  q   = (int)(row % SEQ);
    __half* p = scores + row * (long)SEQ;
    const int tid  = threadIdx.x;
    const int len  = q + 1;
    const int lenR = ((q >> 7) + 1) << 7;

    __shared__ float red[8];

    float v[8];
    float s = 0.f;
#pragma unroll
    for (int j = 0; j < 8; j++) {
        int i = tid + j * 256;
        v[j] = (i < len) ? __expf(__half2float(p[i])) : 0.f;
        s += v[j];
    }
#pragma unroll
    for (int o = 16; o > 0; o >>= 1) s += __shfl_xor_sync(0xffffffffu, s, o);
    if ((tid & 31) == 0) red[tid >> 5] = s;
    __syncthreads();
    float s_all = 0.f;
#pragma unroll
    for (int w = 0; w < 8; w++) s_all += red[w];
    const float inv = 1.f / s_all;

#pragma unroll
    for (int j = 0; j < 8; j++) {
        int i = tid + j * 256;
        if (i < lenR)
            p[i] = __float2half_rn((i < len) ? v[j] * inv : 0.f);
    }
}

// ---------------------------------------------------------------------------
extern "C" void kernel_launch(void* const* d_in, const int* in_sizes, int n_in,
                              void* d_out, int out_size)
{
    const float* x = (const float*)d_in[0];
    const float* W = (const float*)d_in[1];
    float* out = (float*)d_out;

    __half *scoresh, *xh, *xTh, *attnh, *Wh;
    cudaGetSymbolAddress((void**)&scoresh, g_scoresh);
    cudaGetSymbolAddress((void**)&xh, g_xh);
    cudaGetSymbolAddress((void**)&xTh, g_xTh);
    cudaGetSymbolAddress((void**)&attnh, g_attnh);
    cudaGetSymbolAddress((void**)&Wh, g_Wh);

    cudaFuncSetAttribute(gemm_h,
                         cudaFuncAttributeMaxDynamicSharedMemorySize, DSMEM_SZ);

    int dev = 0, nsm = 148;
    cudaGetDevice(&dev);
    cudaDeviceGetAttribute(&nsm, cudaDevAttrMultiProcessorCount, dev);
    const int pgrid = nsm * 2;

    const float scale = 1.0f / 32.0f;

    conv_x<<<dim3(SEQ / 32, DIM / 32, BATCH), 256>>>(x, xh, xTh);
    conv_W<<<(DIM * DIM / 4 + 255) / 256, 256>>>(W, Wh, (long)DIM * DIM / 4);

    // 1) scores = scale * x x^T  (fp16 out, causal tiles only; mode 1)
    {
        const int ntm = SEQ / TM;                 // 16
        const int tpb = ntm * (ntm + 1) / 2;      // 136
        const int ntiles = BATCH * tpb;           // 1088
        gemm_h<<<min(ntiles, pgrid), 128, DSMEM_SZ>>>(
            xh, xh, scoresh, DIM, DIM, DIM, SEQ,
            (long)SEQ * DIM, (long)SEQ * DIM, (long)SEQ * SEQ,
            scale, 1, ntm, SEQ / TN, BATCH, tpb, ntiles, 1);
    }

    // 2) causal softmax in place -> P
    softmax_kernel<<<BATCH * SEQ, 256>>>(scoresh);

    // 3) attn = P x  (fp16 out, k-limited, LPT order; mode 2)
    {
        const int ntm = SEQ / TM;                 // 16
        const int ntn = DIM / TN;                 // 8
        const int ntiles = BATCH * ntm * ntn;     // 1024
        gemm_h<<<min(ntiles, pgrid), 128, DSMEM_SZ>>>(
            scoresh, xTh, attnh, SEQ, SEQ, SEQ, DIM,
            (long)SEQ * SEQ, (long)DIM * SEQ, (long)SEQ * DIM,
            1.0f, 2, ntm, ntn, BATCH, 0, ntiles, 1);
    }

    // 4) y = attn W^T  (fp32 out; mode 0, batch folded into M)
    {
        const int ntm = (BATCH * SEQ) / TM;       // 128
        const int ntn = DIM / TN;                 // 8
        const int ntiles = ntm * ntn;             // 1024
        gemm_h<<<min(ntiles, pgrid), 128, DSMEM_SZ>>>(
            attnh, Wh, out, DIM, DIM, DIM, DIM,
            0, 0, 0,
            1.0f, 0, ntm, ntn, 1, 0, ntiles, 0);
    }
}

// round 15
// speedup vs baseline: 1.0674x; 1.0095x over previous
#include <cuda_runtime.h>
#include <cuda_fp16.h>
#include <cstdint>
#include <math.h>

// ===========================================================================
// B=8, S=2048, D=1024 fp32.
//   scores = causal(x x^T / 32); P = softmax(scores); attn = P x; y = attn W^T
// GEMM engine: mma.sync.m16n8k16 FP16, CTA tile 128x128 (4 warps x 64x64),
// CKH=32, 4-stage cp.async pipeline, ldmatrix b16, 2 CTAs/SM, persistent
// grid with in-kernel tile decode. NEW: odd warps traverse the chunk's two
// k-steps in reverse order, de-phasing crossbar (ldsm) and tensor (mma) use
// across warps. Softmax is uint4-vectorized.
// ===========================================================================

#define BATCH 8
#define SEQ   2048
#define DIM   1024

#define TM 128
#define TN 128
#define CKH 32                 // halves per chunk (64 B rows)
#define LDH 40                 // smem row stride in halves (80 B, conflict-free)
#define NSTAGE 4
#define A_BYTES (TM * LDH * 2)            // 10240
#define B_BYTES (TN * LDH * 2)            // 10240
#define STAGE_BYTES (A_BYTES + B_BYTES)   // 20480
#define DSMEM_SZ (NSTAGE * STAGE_BYTES)   // 81920 B (x2 CTAs = 160 KB)

static __device__ __half g_scoresh[(long)BATCH * SEQ * SEQ]; // fp16 scores -> P in place
static __device__ __half g_xh[(long)BATCH * SEQ * DIM];
static __device__ __half g_xTh[(long)BATCH * DIM * SEQ];
static __device__ __half g_attnh[(long)BATCH * SEQ * DIM];
static __device__ __half g_Wh[DIM * DIM];

// ---------------------------------------------------------------- helpers --
__device__ __forceinline__ uint32_t smem_u32(const void* p) {
    uint32_t a;
    asm("{ .reg .u64 t; cvta.to.shared.u64 t, %1; cvt.u32.u64 %0, t; }"
        : "=r"(a) : "l"(p));
    return a;
}
__device__ __forceinline__ void cp_async16(uint32_t s, const void* g) {
    asm volatile("cp.async.cg.shared.global [%0], [%1], 16;" :: "r"(s), "l"(g));
}
#define CP_COMMIT() asm volatile("cp.async.commit_group;" ::: "memory")
#define CP_WAIT(n)  asm volatile("cp.async.wait_group %0;" :: "n"(n) : "memory")

__device__ __forceinline__ void mma_f16(float c[4], const uint32_t a[4], const uint32_t b[2]) {
    asm volatile(
        "mma.sync.aligned.m16n8k16.row.col.f32.f16.f16.f32 "
        "{%0,%1,%2,%3}, {%4,%5,%6,%7}, {%8,%9}, {%0,%1,%2,%3};"
        : "+f"(c[0]), "+f"(c[1]), "+f"(c[2]), "+f"(c[3])
        : "r"(a[0]), "r"(a[1]), "r"(a[2]), "r"(a[3]), "r"(b[0]), "r"(b[1]));
}
__device__ __forceinline__ void ldsm4(uint32_t r[4], uint32_t addr) {
    asm volatile("ldmatrix.sync.aligned.m8n8.x4.shared.b16 {%0,%1,%2,%3}, [%4];"
                 : "=r"(r[0]), "=r"(r[1]), "=r"(r[2]), "=r"(r[3]) : "r"(addr));
}

// ---------------------------------------------------------------- GEMM NT --
// C[m,n] = scale * sum_k A[m,k] * B[n,k]   (A,B fp16 K-contiguous), persistent.
__global__ __launch_bounds__(128, 2) void gemm_h(
    const __half* __restrict__ A, const __half* __restrict__ B, void* __restrict__ Cv,
    int K, int lda, int ldb, int ldc,
    long sA, long sB, long sC,
    float scale, int mode, int ntm, int ntn, int nb, int tpb, int ntiles,
    int outHalf)
{
    extern __shared__ char smem[];

    const int tid   = threadIdx.x;
    const int lane  = tid & 31;
    const int wid   = tid >> 5;            // 0..3
    const int warpM = wid & 1;
    const int warpN = wid >> 1;
    const int qr    = lane >> 2;
    const int qk    = lane & 3;
    const int kphase = (wid & 1) << 4;     // odd warps start at kstep 1

    const uint32_t sbase = smem_u32(smem);

    // ldmatrix lane addressing (validated Rounds 9-14)
    const int a_row_l = (((lane >> 3) & 1) << 3) + (lane & 7);
    const int a_kh    = ((lane >> 4) & 1) << 3;
    const int b_row_l = (((lane >> 4) & 1) << 3) + (lane & 7);
    const int b_kh    = ((lane >> 3) & 1) << 3;
    uint32_t a_off[4], b_off[4];
#pragma unroll
    for (int mf = 0; mf < 4; mf++)
        a_off[mf] = (uint32_t)((warpM * 64 + mf * 16 + a_row_l) * (LDH * 2) + a_kh * 2);
#pragma unroll
    for (int p = 0; p < 4; p++)
        b_off[p] = (uint32_t)(A_BYTES + (warpN * 64 + p * 16 + b_row_l) * (LDH * 2) + b_kh * 2);

    for (int t = blockIdx.x; t < ntiles; t += gridDim.x) {
        // ---- tile decode ----
        int b, my, nx;
        if (mode == 1) {                       // causal triangular list
            b = t / tpb;
            int r = t - b * tpb;
            int lo = (int)((sqrtf(8.f * (float)r + 1.f) - 1.f) * 0.5f);
            while ((lo + 1) * (lo + 2) / 2 <= r) lo++;
            while (lo * (lo + 1) / 2 > r) lo--;
            my = lo;
            nx = r - lo * (lo + 1) / 2;
        } else if (mode == 2) {                // k-limited, longest rows first
            int pg = ntn * nb;
            my = ntm - 1 - t / pg;
            int rem = t - (t / pg) * pg;
            nx = rem / nb;
            b  = rem - nx * nb;
        } else {                               // dense linear
            b = 0;
            my = t / ntn;
            nx = t - my * ntn;
        }

        const __half* Ab = A + (long)b * sA;
        const __half* Bb = B + (long)b * sB;
        const int m0 = my * TM;
        const int n0 = nx * TN;
        const int kmax = (mode == 2) ? min(K, m0 + TM) : K;
        const int nch  = kmax / CKH;

        float acc[32][4];
#pragma unroll
        for (int i = 0; i < 32; i++)
#pragma unroll
            for (int j = 0; j < 4; j++) acc[i][j] = 0.f;

        auto load_stage = [&](int s, int c) {
            const uint32_t st = sbase + (uint32_t)(s * STAGE_BYTES);
            const char* gA = (const char*)(Ab + (long)m0 * lda + c * CKH);
            const char* gB = (const char*)(Bb + (long)n0 * ldb + c * CKH);
#pragma unroll
            for (int i = 0; i < 4; i++) {
                int idx = tid + i * 128;       // 0..511
                int row = idx >> 2;
                int ch  = (idx & 3) << 4;
                cp_async16(st + (uint32_t)(row * (LDH * 2)) + ch,
                           gA + (long)row * lda * 2 + ch);
            }
#pragma unroll
            for (int i = 0; i < 4; i++) {
                int idx = tid + i * 128;
                int row = idx >> 2;
                int ch  = (idx & 3) << 4;
                cp_async16(st + (uint32_t)(A_BYTES + row * (LDH * 2)) + ch,
                           gB + (long)row * ldb * 2 + ch);
            }
        };

#pragma unroll
        for (int s = 0; s < NSTAGE - 1; s++) {
            if (s < nch) load_stage(s, s);
            CP_COMMIT();
        }

        for (int c = 0; c < nch; c++) {
            CP_WAIT(NSTAGE - 2);
            __syncthreads();

            const int pf = c + NSTAGE - 1;
            if (pf < nch) load_stage(pf % NSTAGE, pf);
            CP_COMMIT();

            const uint32_t st = sbase + (uint32_t)((c % NSTAGE) * STAGE_BYTES);

#pragma unroll
            for (int kx = 0; kx < 2; kx++) {
                // de-phase: even warps do ksteps {0,1}, odd warps {1,0}
                const uint32_t kb = (uint32_t)(((kx << 4) ^ kphase) * 2);
                uint32_t a[4][4], bb[4][4];
#pragma unroll
                for (int mf = 0; mf < 4; mf++)
                    ldsm4(a[mf], st + a_off[mf] + kb);
#pragma unroll
                for (int p = 0; p < 4; p++)
                    ldsm4(bb[p], st + b_off[p] + kb);
#pragma unroll
                for (int mf = 0; mf < 4; mf++)
#pragma unroll
                    for (int nf = 0; nf < 8; nf++)
                        mma_f16(acc[mf * 8 + nf], a[mf], &bb[nf >> 1][(nf & 1) << 1]);
            }
        }

        // epilogue
        if (outHalf) {
            __half* C = (__half*)Cv + (long)b * sC;
#pragma unroll
            for (int mf = 0; mf < 4; mf++) {
                const int m = m0 + warpM * 64 + mf * 16 + qr;
#pragma unroll
                for (int nf = 0; nf < 8; nf++) {
                    const int n = n0 + warpN * 64 + nf * 8 + 2 * qk;
                    float* c0 = acc[mf * 8 + nf];
                    *(__half2*)&C[(long)m * ldc + n] =
                        __floats2half2_rn(c0[0] * scale, c0[1] * scale);
                    *(__half2*)&C[(long)(m + 8) * ldc + n] =
                        __floats2half2_rn(c0[2] * scale, c0[3] * scale);
                }
            }
        } else {
            float* C = (float*)Cv + (long)b * sC;
#pragma unroll
            for (int mf = 0; mf < 4; mf++) {
                const int m = m0 + warpM * 64 + mf * 16 + qr;
#pragma unroll
                for (int nf = 0; nf < 8; nf++) {
                    const int n = n0 + warpN * 64 + nf * 8 + 2 * qk;
                    float* c0 = acc[mf * 8 + nf];
                    *(float2*)&C[(long)m * ldc + n] =
                        make_float2(c0[0] * scale, c0[1] * scale);
                    *(float2*)&C[(long)(m + 8) * ldc + n] =
                        make_float2(c0[2] * scale, c0[3] * scale);
                }
            }
        }

        // drain async pipe + protect smem slots before next tile's prologue
        CP_WAIT(0);
        __syncthreads();
    }
}

// ---------------------------------------------------------------- prep -----
__global__ __launch_bounds__(256) void conv_x(
    const float* __restrict__ x, __half* __restrict__ xh, __half* __restrict__ xT)
{
    __shared__ float t[32][33];
    const int b  = blockIdx.z;
    const int s0 = blockIdx.x * 32;
    const int d0 = blockIdx.y * 32;
    const float* xb = x + (long)b * SEQ * DIM;
    __half* xhb = xh + (long)b * SEQ * DIM;
    __half* xTb = xT + (long)b * DIM * SEQ;
    const int tx = threadIdx.x & 31;
    const int tg = threadIdx.x >> 5;
#pragma unroll
    for (int r = 0; r < 4; r++) {
        int row = tg * 4 + r;
        float v = xb[(long)(s0 + row) * DIM + d0 + tx];
        t[row][tx] = v;
        xhb[(long)(s0 + row) * DIM + d0 + tx] = __float2half_rn(v);
    }
    __syncthreads();
#pragma unroll
    for (int r = 0; r < 4; r++) {
        int row = tg * 4 + r;
        xTb[(long)(d0 + row) * SEQ + s0 + tx] = __float2half_rn(t[tx][row]);
    }
}

__global__ __launch_bounds__(256) void conv_W(const float* __restrict__ W,
                                              __half* __restrict__ Wh, long n4)
{
    long i = (long)blockIdx.x * blockDim.x + threadIdx.x;
    if (i >= n4) return;
    float4 v = ((const float4*)W)[i];
    __half2* o = (__half2*)Wh + i * 2;
    o[0] = __floats2half2_rn(v.x, v.y);
    o[1] = __floats2half2_rn(v.z, v.w);
}

// ---------------------------------------------------------------- softmax --
// in-place causal softmax (fp16), no max subtraction (scores bounded; softmax
// shift-invariant). uint4-vectorized: each thread owns 8 contiguous halves.
// Writes only cols < roundUp(q+1,128).
__global__ __launch_bounds__(256) void softmax_kernel(__half* __restrict__ scores)
{
    const long row = blockIdx.x;
    const int  q   = (int)(row % SEQ);
    __half* p = scores + row * (long)SEQ;
    const int tid  = threadIdx.x;
    const int len  = q + 1;
    const int lenR = ((q >> 7) + 1) << 7;
    const int i8   = tid << 3;             // this thread's 8-half slot

    __shared__ float red[8];

    uint4 u = *(const uint4*)(p + i8);
    __half2* h = (__half2*)&u;
    float v[8];
#pragma unroll
    for (int j = 0; j < 4; j++) {
        float2 f = __half22float2(h[j]);
        v[2 * j]     = f.x;
        v[2 * j + 1] = f.y;
    }

    float s = 0.f;
#pragma unroll
    for (int j = 0; j < 8; j++) {
        v[j] = (i8 + j < len) ? __expf(v[j]) : 0.f;
        s += v[j];
    }
#pragma unroll
    for (int o = 16; o > 0; o >>= 1) s += __shfl_xor_sync(0xffffffffu, s, o);
    if ((tid & 31) == 0) red[tid >> 5] = s;
    __syncthreads();
    float s_all = 0.f;
#pragma unroll
    for (int w = 0; w < 8; w++) s_all += red[w];
    const float inv = 1.f / s_all;

    if (i8 < lenR) {
#pragma unroll
        for (int j = 0; j < 4; j++)
            h[j] = __floats2half2_rn(v[2 * j] * inv, v[2 * j + 1] * inv);
        *(uint4*)(p + i8) = u;
    }
}

// ---------------------------------------------------------------------------
extern "C" void kernel_launch(void* const* d_in, const int* in_sizes, int n_in,
                              void* d_out, int out_size)
{
    const float* x = (const float*)d_in[0];
    const float* W = (const float*)d_in[1];
    float* out = (float*)d_out;

    __half *scoresh, *xh, *xTh, *attnh, *Wh;
    cudaGetSymbolAddress((void**)&scoresh, g_scoresh);
    cudaGetSymbolAddress((void**)&xh, g_xh);
    cudaGetSymbolAddress((void**)&xTh, g_xTh);
    cudaGetSymbolAddress((void**)&attnh, g_attnh);
    cudaGetSymbolAddress((void**)&Wh, g_Wh);

    cudaFuncSetAttribute(gemm_h,
                         cudaFuncAttributeMaxDynamicSharedMemorySize, DSMEM_SZ);

    int dev = 0, nsm = 148;
    cudaGetDevice(&dev);
    cudaDeviceGetAttribute(&nsm, cudaDevAttrMultiProcessorCount, dev);
    const int pgrid = nsm * 2;

    const float scale = 1.0f / 32.0f;

    conv_x<<<dim3(SEQ / 32, DIM / 32, BATCH), 256>>>(x, xh, xTh);
    conv_W<<<(DIM * DIM / 4 + 255) / 256, 256>>>(W, Wh, (long)DIM * DIM / 4);

    // 1) scores = scale * x x^T  (fp16 out, causal tiles only; mode 1)
    {
        const int ntm = SEQ / TM;                 // 16
        const int tpb = ntm * (ntm + 1) / 2;      // 136
        const int ntiles = BATCH * tpb;           // 1088
        gemm_h<<<min(ntiles, pgrid), 128, DSMEM_SZ>>>(
            xh, xh, scoresh, DIM, DIM, DIM, SEQ,
            (long)SEQ * DIM, (long)SEQ * DIM, (long)SEQ * SEQ,
            scale, 1, ntm, SEQ / TN, BATCH, tpb, ntiles, 1);
    }

    // 2) causal softmax in place -> P
    softmax_kernel<<<BATCH * SEQ, 256>>>(scoresh);

    // 3) attn = P x  (fp16 out, k-limited, LPT order; mode 2)
    {
        const int ntm = SEQ / TM;                 // 16
        const int ntn = DIM / TN;                 // 8
        const int ntiles = BATCH * ntm * ntn;     // 1024
        gemm_h<<<min(ntiles, pgrid), 128, DSMEM_SZ>>>(
            scoresh, xTh, attnh, SEQ, SEQ, SEQ, DIM,
            (long)SEQ * SEQ, (long)DIM * SEQ, (long)SEQ * DIM,
            1.0f, 2, ntm, ntn, BATCH, 0, ntiles, 1);
    }

    // 4) y = attn W^T  (fp32 out; mode 0, batch folded into M)
    {
        const int ntm = (BATCH * SEQ) / TM;       // 128
        const int ntn = DIM / TN;                 // 8
        const int ntiles = ntm * ntn;             // 1024
        gemm_h<<<min(ntiles, pgrid), 128, DSMEM_SZ>>>(
            attnh, Wh, out, DIM, DIM, DIM, DIM,
            0, 0, 0,
            1.0f, 0, ntm, ntn, 1, 0, ntiles, 0);
    }
}